// round 1
// baseline (speedup 1.0000x reference)
#include <cuda_runtime.h>
#include <math.h>

#define Bq 256
#define Nq 256
#define Dq 512
#define Cq 1024

// Scratch (device globals — no allocation allowed)
__device__ float g_txtn[Cq * Dq];     // normalized text features  (2 MB)
__device__ float g_rnorm[Bq * Nq];    // 1/||toks[b,n]||
__device__ float g_simsgt[Bq * Nq];   // toks_norm . txt_norm[gt[b]]
__device__ float g_wcoef[Bq * Nq];    // softmax weight * rnorm
__device__ float g_pooled[Bq * Dq];   // weighted-pooled raw tokens (normalized via wcoef)
__device__ float g_logits[Bq * Cq];
__device__ float g_nll[Bq];

__device__ __forceinline__ float warp_sum(float v) {
#pragma unroll
    for (int o = 16; o; o >>= 1) v += __shfl_xor_sync(0xffffffffu, v, o);
    return v;
}

// ---------------------------------------------------------------------------
// K1: L2-normalize text features. One warp per row. grid = C/8, block = 256.
// ---------------------------------------------------------------------------
__global__ void k_txtnorm(const float* __restrict__ txt) {
    int w = threadIdx.x >> 5, lane = threadIdx.x & 31;
    int row = blockIdx.x * 8 + w;
    const float4* src = (const float4*)(txt + (size_t)row * Dq);
    float4* dst = (float4*)(g_txtn + (size_t)row * Dq);
    float4 v[4];
    float ss = 0.f;
#pragma unroll
    for (int i = 0; i < 4; i++) {
        v[i] = src[lane + 32 * i];
        ss += v[i].x * v[i].x + v[i].y * v[i].y + v[i].z * v[i].z + v[i].w * v[i].w;
    }
    ss = warp_sum(ss);
    float rn = 1.f / fmaxf(sqrtf(ss), 1e-12f);
#pragma unroll
    for (int i = 0; i < 4; i++) {
        float4 o;
        o.x = v[i].x * rn; o.y = v[i].y * rn; o.z = v[i].z * rn; o.w = v[i].w * rn;
        dst[lane + 32 * i] = o;
    }
}

// ---------------------------------------------------------------------------
// K2: per-(b,n) row: rnorm = 1/||toks||, simsgt = rnorm * toks . txt_norm[gt[b]]
// grid = B, block = 256 (8 warps, 32 rows per warp). Streams 128 MB.
// ---------------------------------------------------------------------------
__global__ void k_simsgt(const float* __restrict__ toks, const int* __restrict__ gt) {
    __shared__ float4 stxt[Dq / 4];
    int b = blockIdx.x;
    int tid = threadIdx.x;
    int g = gt[b];
    if (tid < Dq / 4) stxt[tid] = ((const float4*)(g_txtn + (size_t)g * Dq))[tid];
    __syncthreads();

    int w = tid >> 5, lane = tid & 31;
    const float4* bbase = (const float4*)(toks + (size_t)b * Nq * Dq);
#pragma unroll 1
    for (int n = w * 32; n < w * 32 + 32; n++) {
        const float4* row = bbase + (size_t)n * (Dq / 4);
        float ss = 0.f, dp = 0.f;
#pragma unroll
        for (int i = 0; i < 4; i++) {
            float4 t = row[lane + 32 * i];
            float4 x = stxt[lane + 32 * i];
            ss += t.x * t.x + t.y * t.y + t.z * t.z + t.w * t.w;
            dp += t.x * x.x + t.y * x.y + t.z * x.z + t.w * x.w;
        }
        ss = warp_sum(ss);
        dp = warp_sum(dp);
        if (lane == 0) {
            float rn = 1.f / fmaxf(sqrtf(ss), 1e-12f);
            g_rnorm[b * Nq + n] = rn;
            g_simsgt[b * Nq + n] = dp * rn;
        }
    }
}

// ---------------------------------------------------------------------------
// K3: softmax over N of simsgt/attn_tau; combine with rnorm into wcoef.
// grid = B, block = 256 (N threads).
// ---------------------------------------------------------------------------
__global__ void k_softmax(const float* __restrict__ p_log_attn_tau) {
    __shared__ float red[Nq];
    int b = blockIdx.x, n = threadIdx.x;
    float at = expf(*p_log_attn_tau);
    at = fminf(fmaxf(at, 0.01f), 1.0f);
    float x = g_simsgt[b * Nq + n] / at;

    red[n] = x;
    __syncthreads();
#pragma unroll
    for (int s = 128; s; s >>= 1) {
        if (n < s) red[n] = fmaxf(red[n], red[n + s]);
        __syncthreads();
    }
    float mx = red[0];
    __syncthreads();

    float e = expf(x - mx);
    red[n] = e;
    __syncthreads();
#pragma unroll
    for (int s = 128; s; s >>= 1) {
        if (n < s) red[n] += red[n + s];
        __syncthreads();
    }
    float wv = e / red[0];
    g_wcoef[b * Nq + n] = wv * g_rnorm[b * Nq + n];
}

// ---------------------------------------------------------------------------
// K4: pooled[b,:] = sum_n wcoef[b,n] * toks[b,n,:]. grid = B, block = 128.
// Each thread owns one float4 column slot. Streams 128 MB.
// ---------------------------------------------------------------------------
__global__ void k_pool(const float* __restrict__ toks) {
    __shared__ float sc[Nq];
    int b = blockIdx.x, tid = threadIdx.x;
    for (int i = tid; i < Nq; i += 128) sc[i] = g_wcoef[b * Nq + i];
    __syncthreads();

    const float4* base = (const float4*)(toks + (size_t)b * Nq * Dq);
    float4 acc = make_float4(0.f, 0.f, 0.f, 0.f);
#pragma unroll 8
    for (int n = 0; n < Nq; n++) {
        float4 t = base[(size_t)n * (Dq / 4) + tid];
        float c = sc[n];
        acc.x = fmaf(c, t.x, acc.x);
        acc.y = fmaf(c, t.y, acc.y);
        acc.z = fmaf(c, t.z, acc.z);
        acc.w = fmaf(c, t.w, acc.w);
    }
    ((float4*)(g_pooled + (size_t)b * Dq))[tid] = acc;
}

// ---------------------------------------------------------------------------
// K5: logits = pooled [B,D] @ txt_norm^T [D,C]. 64x64 tile, BK=32, 256 thr,
// 4x4 per thread. grid = (C/64, B/64) = (16, 4).
// ---------------------------------------------------------------------------
__global__ void k_gemm() {
    __shared__ float As[32][68];  // [k][row], pad 68 keeps float4-aligned rows
    __shared__ float Bs[32][68];
    int tid = threadIdx.x;
    int c0 = blockIdx.x * 64;
    int b0 = blockIdx.y * 64;
    int tx = tid & 15, ty = tid >> 4;

    float acc[4][4];
#pragma unroll
    for (int i = 0; i < 4; i++)
#pragma unroll
        for (int j = 0; j < 4; j++) acc[i][j] = 0.f;

    for (int k0 = 0; k0 < Dq; k0 += 32) {
#pragma unroll
        for (int i = 0; i < 8; i++) {
            int idx = tid + i * 256;
            int r = idx >> 5;
            int kk = idx & 31;
            As[kk][r] = g_pooled[(size_t)(b0 + r) * Dq + k0 + kk];
            Bs[kk][r] = g_txtn[(size_t)(c0 + r) * Dq + k0 + kk];
        }
        __syncthreads();
#pragma unroll
        for (int kk = 0; kk < 32; kk++) {
            float4 a4 = *(const float4*)&As[kk][ty * 4];
            float4 b4 = *(const float4*)&Bs[kk][tx * 4];
            float a[4] = {a4.x, a4.y, a4.z, a4.w};
            float bb[4] = {b4.x, b4.y, b4.z, b4.w};
#pragma unroll
            for (int i = 0; i < 4; i++)
#pragma unroll
                for (int j = 0; j < 4; j++) acc[i][j] = fmaf(a[i], bb[j], acc[i][j]);
        }
        __syncthreads();
    }
#pragma unroll
    for (int i = 0; i < 4; i++)
#pragma unroll
        for (int j = 0; j < 4; j++)
            g_logits[(size_t)(b0 + ty * 4 + i) * Cq + c0 + tx * 4 + j] = acc[i][j];
}

// ---------------------------------------------------------------------------
// K6: per-b cross entropy: nll[b] = logsumexp(logits/tau) - logits[gt]/tau.
// grid = B, block = 256 (each thread holds 4 of the 1024 logits).
// ---------------------------------------------------------------------------
__global__ void k_ce(const float* __restrict__ p_log_tau, const int* __restrict__ gt) {
    __shared__ float red[256];
    int b = blockIdx.x, tid = threadIdx.x;
    float tau = expf(*p_log_tau);
    tau = fminf(fmaxf(tau, 0.01f), 1.0f);
    float inv = 1.f / tau;

    float l[4];
    float mx = -1e30f;
#pragma unroll
    for (int i = 0; i < 4; i++) {
        l[i] = g_logits[(size_t)b * Cq + tid + i * 256] * inv;
        mx = fmaxf(mx, l[i]);
    }
    red[tid] = mx;
    __syncthreads();
#pragma unroll
    for (int s = 128; s; s >>= 1) {
        if (tid < s) red[tid] = fmaxf(red[tid], red[tid + s]);
        __syncthreads();
    }
    mx = red[0];
    __syncthreads();

    float sum = 0.f;
#pragma unroll
    for (int i = 0; i < 4; i++) sum += expf(l[i] - mx);
    red[tid] = sum;
    __syncthreads();
#pragma unroll
    for (int s = 128; s; s >>= 1) {
        if (tid < s) red[tid] += red[tid + s];
        __syncthreads();
    }
    if (tid == 0) {
        int g = gt[b];
        float xg = g_logits[(size_t)b * Cq + g] * inv;
        g_nll[b] = logf(red[0]) + mx - xg;
    }
}

// ---------------------------------------------------------------------------
// K7: mean over B. 1 block, 256 threads.
// ---------------------------------------------------------------------------
__global__ void k_mean(float* __restrict__ out) {
    __shared__ float red[Bq];
    int tid = threadIdx.x;
    red[tid] = g_nll[tid];
    __syncthreads();
#pragma unroll
    for (int s = 128; s; s >>= 1) {
        if (tid < s) red[tid] += red[tid + s];
        __syncthreads();
    }
    if (tid == 0) out[0] = red[0] * (1.0f / (float)Bq);
}

// ---------------------------------------------------------------------------
extern "C" void kernel_launch(void* const* d_in, const int* in_sizes, int n_in,
                              void* d_out, int out_size) {
    const float* toks         = (const float*)d_in[0];  // [B,N,D] f32
    const float* txt          = (const float*)d_in[1];  // [C,D]   f32
    const float* log_tau      = (const float*)d_in[2];  // scalar
    const float* log_attn_tau = (const float*)d_in[3];  // scalar
    const int*   gt           = (const int*)d_in[4];    // [B] int32

    k_txtnorm<<<Cq / 8, 256>>>(txt);
    k_simsgt<<<Bq, 256>>>(toks, gt);
    k_softmax<<<Bq, 256>>>(log_attn_tau);
    k_pool<<<Bq, 128>>>(toks);
    dim3 g5(Cq / 64, Bq / 64);
    k_gemm<<<g5, 256>>>();
    k_ce<<<Bq, 256>>>(log_tau, gt);
    k_mean<<<1, 256>>>((float*)d_out);
}

// round 2
// speedup vs baseline: 1.6374x; 1.6374x over previous
#include <cuda_runtime.h>
#include <math.h>

#define Bq 256
#define Nq 256
#define Dq 512
#define Cq 1024
#define NCHUNK 8
#define CH_ROWS (Nq / NCHUNK)   // 32

// Scratch (device globals — no allocation allowed)
__device__ float g_txtn[Cq * Dq];                 // normalized text features (2 MB)
__device__ float g_rnorm[Bq * Nq];                // 1/||toks[b,n]||
__device__ float g_simsgt[Bq * Nq];               // toks_norm . txt_norm[gt[b]]
__device__ float g_wcoef[Bq * Nq];                // softmax weight * rnorm
__device__ float g_ppart[Bq * NCHUNK * Dq];       // partial pooled (4 MB)
__device__ float g_pooled[Bq * Dq];               // pooled tokens
__device__ float g_logits[Bq * Cq];
__device__ float g_nll[Bq];

__device__ __forceinline__ float warp_sum(float v) {
#pragma unroll
    for (int o = 16; o; o >>= 1) v += __shfl_xor_sync(0xffffffffu, v, o);
    return v;
}

// ---------------------------------------------------------------------------
// K1: L2-normalize text features. One warp per row. grid = C/8, block = 256.
// ---------------------------------------------------------------------------
__global__ void k_txtnorm(const float* __restrict__ txt) {
    int w = threadIdx.x >> 5, lane = threadIdx.x & 31;
    int row = blockIdx.x * 8 + w;
    const float4* src = (const float4*)(txt + (size_t)row * Dq);
    float4* dst = (float4*)(g_txtn + (size_t)row * Dq);
    float4 v[4];
    float ss = 0.f;
#pragma unroll
    for (int i = 0; i < 4; i++) {
        v[i] = src[lane + 32 * i];
        ss += v[i].x * v[i].x + v[i].y * v[i].y + v[i].z * v[i].z + v[i].w * v[i].w;
    }
    ss = warp_sum(ss);
    float rn = 1.f / fmaxf(sqrtf(ss), 1e-12f);
#pragma unroll
    for (int i = 0; i < 4; i++) {
        float4 o;
        o.x = v[i].x * rn; o.y = v[i].y * rn; o.z = v[i].z * rn; o.w = v[i].w * rn;
        dst[lane + 32 * i] = o;
    }
}

// ---------------------------------------------------------------------------
// K2: one WARP per (b,n) row: rnorm = 1/||toks||, simsgt = rnorm * toks.txtn[gt]
// grid = B*N/8 = 8192, block = 256 (8 warps). Streams 128 MB; txtn is L2-hot.
// ---------------------------------------------------------------------------
__global__ void k_simsgt(const float* __restrict__ toks, const int* __restrict__ gt) {
    int w = threadIdx.x >> 5, lane = threadIdx.x & 31;
    int row = blockIdx.x * 8 + w;                // 0 .. B*N-1
    int b = row >> 8;                            // Nq = 256
    int g = __ldg(&gt[b]);
    const float4* t = (const float4*)(toks + (size_t)row * Dq);
    const float4* x = (const float4*)(g_txtn + (size_t)g * Dq);
    float ss = 0.f, dp = 0.f;
#pragma unroll
    for (int i = 0; i < 4; i++) {
        float4 tv = t[lane + 32 * i];
        float4 xv = x[lane + 32 * i];
        ss += tv.x * tv.x + tv.y * tv.y + tv.z * tv.z + tv.w * tv.w;
        dp += tv.x * xv.x + tv.y * xv.y + tv.z * xv.z + tv.w * xv.w;
    }
    ss = warp_sum(ss);
    dp = warp_sum(dp);
    if (lane == 0) {
        float rn = 1.f / fmaxf(sqrtf(ss), 1e-12f);
        g_rnorm[row] = rn;
        g_simsgt[row] = dp * rn;
    }
}

// ---------------------------------------------------------------------------
// K3: softmax over N of simsgt/attn_tau; combine with rnorm into wcoef.
// grid = B, block = 256.
// ---------------------------------------------------------------------------
__global__ void k_softmax(const float* __restrict__ p_log_attn_tau) {
    __shared__ float red[Nq];
    int b = blockIdx.x, n = threadIdx.x;
    float at = expf(*p_log_attn_tau);
    at = fminf(fmaxf(at, 0.01f), 1.0f);
    float x = g_simsgt[b * Nq + n] / at;

    red[n] = x;
    __syncthreads();
#pragma unroll
    for (int s = 128; s; s >>= 1) {
        if (n < s) red[n] = fmaxf(red[n], red[n + s]);
        __syncthreads();
    }
    float mx = red[0];
    __syncthreads();

    float e = expf(x - mx);
    red[n] = e;
    __syncthreads();
#pragma unroll
    for (int s = 128; s; s >>= 1) {
        if (n < s) red[n] += red[n + s];
        __syncthreads();
    }
    float wv = e / red[0];
    g_wcoef[b * Nq + n] = wv * g_rnorm[b * Nq + n];
}

// ---------------------------------------------------------------------------
// K4: partial pool. grid = (NCHUNK, B), block = 128. Each block accumulates
// 32 token rows into a Dq-wide partial. Streams 128 MB with 2048 CTAs.
// ---------------------------------------------------------------------------
__global__ void k_pool(const float* __restrict__ toks) {
    __shared__ float sc[CH_ROWS];
    int ch = blockIdx.x, b = blockIdx.y;
    int tid = threadIdx.x;
    if (tid < CH_ROWS) sc[tid] = g_wcoef[b * Nq + ch * CH_ROWS + tid];
    __syncthreads();

    const float4* base =
        (const float4*)(toks + ((size_t)b * Nq + ch * CH_ROWS) * Dq);
    float4 acc = make_float4(0.f, 0.f, 0.f, 0.f);
#pragma unroll 8
    for (int n = 0; n < CH_ROWS; n++) {
        float4 t = base[(size_t)n * (Dq / 4) + tid];
        float c = sc[n];
        acc.x = fmaf(c, t.x, acc.x);
        acc.y = fmaf(c, t.y, acc.y);
        acc.z = fmaf(c, t.z, acc.z);
        acc.w = fmaf(c, t.w, acc.w);
    }
    ((float4*)(g_ppart + ((size_t)(b * NCHUNK + ch)) * Dq))[tid] = acc;
}

// ---------------------------------------------------------------------------
// K4b: reduce partials. grid = B, block = 128.
// ---------------------------------------------------------------------------
__global__ void k_pool_reduce() {
    int b = blockIdx.x, tid = threadIdx.x;
    const float4* part = (const float4*)(g_ppart + (size_t)b * NCHUNK * Dq);
    float4 acc = make_float4(0.f, 0.f, 0.f, 0.f);
#pragma unroll
    for (int ch = 0; ch < NCHUNK; ch++) {
        float4 p = part[(size_t)ch * (Dq / 4) + tid];
        acc.x += p.x; acc.y += p.y; acc.z += p.z; acc.w += p.w;
    }
    ((float4*)(g_pooled + (size_t)b * Dq))[tid] = acc;
}

// ---------------------------------------------------------------------------
// K5: logits = pooled [B,D] @ txtn^T [D,C]. 32x64 tile, BK=32, 256 thr,
// 2x4 per thread. grid = (C/64, B/32) = (16, 8) = 128 blocks.
// ---------------------------------------------------------------------------
__global__ void k_gemm() {
    __shared__ float As[32][36];
    __shared__ float Bs[32][68];
    int tid = threadIdx.x;
    int c0 = blockIdx.x * 64;
    int b0 = blockIdx.y * 32;
    int tx = tid & 15, ty = tid >> 4;   // tx: 16 col-groups of 4, ty: 16 row-groups of 2

    float acc[2][4];
#pragma unroll
    for (int i = 0; i < 2; i++)
#pragma unroll
        for (int j = 0; j < 4; j++) acc[i][j] = 0.f;

    for (int k0 = 0; k0 < Dq; k0 += 32) {
#pragma unroll
        for (int i = 0; i < 4; i++) {
            int idx = tid + i * 256;            // 0..1023 -> 32 rows x 32 k
            int r = idx >> 5;
            int kk = idx & 31;
            As[kk][r] = g_pooled[(size_t)(b0 + r) * Dq + k0 + kk];
        }
#pragma unroll
        for (int i = 0; i < 8; i++) {
            int idx = tid + i * 256;            // 0..2047 -> 64 rows x 32 k
            int r = idx >> 5;
            int kk = idx & 31;
            Bs[kk][r] = g_txtn[(size_t)(c0 + r) * Dq + k0 + kk];
        }
        __syncthreads();
#pragma unroll
        for (int kk = 0; kk < 32; kk++) {
            float a0 = As[kk][ty * 2];
            float a1 = As[kk][ty * 2 + 1];
            float4 b4 = *(const float4*)&Bs[kk][tx * 4];
            acc[0][0] = fmaf(a0, b4.x, acc[0][0]);
            acc[0][1] = fmaf(a0, b4.y, acc[0][1]);
            acc[0][2] = fmaf(a0, b4.z, acc[0][2]);
            acc[0][3] = fmaf(a0, b4.w, acc[0][3]);
            acc[1][0] = fmaf(a1, b4.x, acc[1][0]);
            acc[1][1] = fmaf(a1, b4.y, acc[1][1]);
            acc[1][2] = fmaf(a1, b4.z, acc[1][2]);
            acc[1][3] = fmaf(a1, b4.w, acc[1][3]);
        }
        __syncthreads();
    }
#pragma unroll
    for (int i = 0; i < 2; i++)
#pragma unroll
        for (int j = 0; j < 4; j++)
            g_logits[(size_t)(b0 + ty * 2 + i) * Cq + c0 + tx * 4 + j] = acc[i][j];
}

// ---------------------------------------------------------------------------
// K6: per-b cross entropy: nll[b] = logsumexp(logits/tau) - logits[gt]/tau.
// grid = B, block = 256.
// ---------------------------------------------------------------------------
__global__ void k_ce(const float* __restrict__ p_log_tau, const int* __restrict__ gt) {
    __shared__ float red[256];
    int b = blockIdx.x, tid = threadIdx.x;
    float tau = expf(*p_log_tau);
    tau = fminf(fmaxf(tau, 0.01f), 1.0f);
    float inv = 1.f / tau;

    float l[4];
    float mx = -1e30f;
#pragma unroll
    for (int i = 0; i < 4; i++) {
        l[i] = g_logits[(size_t)b * Cq + tid + i * 256] * inv;
        mx = fmaxf(mx, l[i]);
    }
    red[tid] = mx;
    __syncthreads();
#pragma unroll
    for (int s = 128; s; s >>= 1) {
        if (tid < s) red[tid] = fmaxf(red[tid], red[tid + s]);
        __syncthreads();
    }
    mx = red[0];
    __syncthreads();

    float sum = 0.f;
#pragma unroll
    for (int i = 0; i < 4; i++) sum += expf(l[i] - mx);
    red[tid] = sum;
    __syncthreads();
#pragma unroll
    for (int s = 128; s; s >>= 1) {
        if (tid < s) red[tid] += red[tid + s];
        __syncthreads();
    }
    if (tid == 0) {
        int g = gt[b];
        float xg = g_logits[(size_t)b * Cq + g] * inv;
        g_nll[b] = logf(red[0]) + mx - xg;
    }
}

// ---------------------------------------------------------------------------
// K7: mean over B. 1 block, 256 threads.
// ---------------------------------------------------------------------------
__global__ void k_mean(float* __restrict__ out) {
    __shared__ float red[Bq];
    int tid = threadIdx.x;
    red[tid] = g_nll[tid];
    __syncthreads();
#pragma unroll
    for (int s = 128; s; s >>= 1) {
        if (tid < s) red[tid] += red[tid + s];
        __syncthreads();
    }
    if (tid == 0) out[0] = red[0] * (1.0f / (float)Bq);
}

// ---------------------------------------------------------------------------
extern "C" void kernel_launch(void* const* d_in, const int* in_sizes, int n_in,
                              void* d_out, int out_size) {
    const float* toks         = (const float*)d_in[0];  // [B,N,D] f32
    const float* txt          = (const float*)d_in[1];  // [C,D]   f32
    const float* log_tau      = (const float*)d_in[2];  // scalar
    const float* log_attn_tau = (const float*)d_in[3];  // scalar
    const int*   gt           = (const int*)d_in[4];    // [B] int32

    k_txtnorm<<<Cq / 8, 256>>>(txt);
    k_simsgt<<<(Bq * Nq) / 8, 256>>>(toks, gt);
    k_softmax<<<Bq, 256>>>(log_attn_tau);
    dim3 gp(NCHUNK, Bq);
    k_pool<<<gp, 128>>>(toks);
    k_pool_reduce<<<Bq, 128>>>();
    dim3 g5(Cq / 64, Bq / 32);
    k_gemm<<<g5, 256>>>();
    k_ce<<<Bq, 256>>>(log_tau, gt);
    k_mean<<<1, 256>>>((float*)d_out);
}

// round 3
// speedup vs baseline: 1.8682x; 1.1410x over previous
#include <cuda_runtime.h>
#include <math.h>

#define Bq 256
#define Nq 256
#define Dq 512
#define Cq 1024
#define NCHUNK 8
#define CH_ROWS (Nq / NCHUNK)   // 32 rows per fused block

// Scratch (device globals — no allocation allowed)
__device__ float  g_txtn[Cq * Dq];                 // normalized text (2 MB)
__device__ float  g_ppart[Bq * NCHUNK * Dq];       // partial weighted sums (4 MB)
__device__ float2 g_meta[Bq * NCHUNK];             // (m, den) per partial
__device__ float  g_pooled[Bq * Dq];               // pooled normalized tokens
__device__ float  g_logits[Bq * Cq];

__device__ __forceinline__ void warp_sum2(float& a, float& b) {
#pragma unroll
    for (int o = 16; o; o >>= 1) {
        a += __shfl_xor_sync(0xffffffffu, a, o);
        b += __shfl_xor_sync(0xffffffffu, b, o);
    }
}

// ---------------------------------------------------------------------------
// K1: L2-normalize text features; also zero the output scalar (for K5 atomics).
// One warp per row. grid = C/8, block = 256.
// ---------------------------------------------------------------------------
__global__ void k_txtnorm(const float* __restrict__ txt, float* __restrict__ out) {
    if (blockIdx.x == 0 && threadIdx.x == 0) out[0] = 0.f;
    int w = threadIdx.x >> 5, lane = threadIdx.x & 31;
    int row = blockIdx.x * 8 + w;
    const float4* src = (const float4*)(txt + (size_t)row * Dq);
    float4* dst = (float4*)(g_txtn + (size_t)row * Dq);
    float4 v[4];
    float ss = 0.f, dummy = 0.f;
#pragma unroll
    for (int i = 0; i < 4; i++) {
        v[i] = src[lane + 32 * i];
        ss += v[i].x * v[i].x + v[i].y * v[i].y + v[i].z * v[i].z + v[i].w * v[i].w;
    }
    warp_sum2(ss, dummy);
    float rn = 1.f / fmaxf(sqrtf(ss), 1e-12f);
#pragma unroll
    for (int i = 0; i < 4; i++) {
        float4 o;
        o.x = v[i].x * rn; o.y = v[i].y * rn; o.z = v[i].z * rn; o.w = v[i].w * rn;
        dst[lane + 32 * i] = o;
    }
}

// ---------------------------------------------------------------------------
// K2 (fused streaming pass): for each (b, chunk of 32 rows), compute per-row
//   s_n = (toks_n . txtn[gt[b]]) / (||toks_n|| * attn_tau)
// and online-softmax-accumulate  vec = sum_n e^{s_n - m} * toks_n/||toks_n||,
// den = sum_n e^{s_n - m}.  Single read of toks (128 MB total).
// grid = (NCHUNK, B) = 2048 blocks, block = 256 (8 warps x 4 rows).
// ---------------------------------------------------------------------------
__global__ void k_fused(const float* __restrict__ toks,
                        const int* __restrict__ gt,
                        const float* __restrict__ p_log_attn_tau) {
    __shared__ float sm[8], sden[8];
    __shared__ float svec[8][Dq];

    int ch = blockIdx.x, b = blockIdx.y;
    int w = threadIdx.x >> 5, lane = threadIdx.x & 31;

    float at = expf(*p_log_attn_tau);
    at = fminf(fmaxf(at, 0.01f), 1.0f);
    float inv_at = 1.f / at;

    int g = __ldg(&gt[b]);
    const float4* xrow = (const float4*)(g_txtn + (size_t)g * Dq);
    float4 xv[4];
#pragma unroll
    for (int i = 0; i < 4; i++) xv[i] = xrow[lane + 32 * i];

    int row0 = b * Nq + ch * CH_ROWS + w * 4;     // this warp's 4 rows
    const float4* base = (const float4*)(toks + (size_t)row0 * Dq);

    float m = -1e30f, den = 0.f;
    float4 acc[4];
#pragma unroll
    for (int i = 0; i < 4; i++) acc[i] = make_float4(0.f, 0.f, 0.f, 0.f);

#pragma unroll
    for (int r = 0; r < 4; r++) {
        float4 tv[4];
#pragma unroll
        for (int i = 0; i < 4; i++) tv[i] = base[(size_t)r * (Dq / 4) + lane + 32 * i];
        float ss = 0.f, dp = 0.f;
#pragma unroll
        for (int i = 0; i < 4; i++) {
            ss += tv[i].x * tv[i].x + tv[i].y * tv[i].y + tv[i].z * tv[i].z + tv[i].w * tv[i].w;
            dp += tv[i].x * xv[i].x + tv[i].y * xv[i].y + tv[i].z * xv[i].z + tv[i].w * xv[i].w;
        }
        warp_sum2(ss, dp);
        float rn = 1.f / fmaxf(sqrtf(ss), 1e-12f);
        float s = dp * rn * inv_at;
        float mnew = fmaxf(m, s);
        float scale = expf(m - mnew);   // 0 on first row
        float e = expf(s - mnew);
        den = den * scale + e;
        float ern = e * rn;
#pragma unroll
        for (int i = 0; i < 4; i++) {
            acc[i].x = fmaf(ern, tv[i].x, acc[i].x * scale);
            acc[i].y = fmaf(ern, tv[i].y, acc[i].y * scale);
            acc[i].z = fmaf(ern, tv[i].z, acc[i].z * scale);
            acc[i].w = fmaf(ern, tv[i].w, acc[i].w * scale);
        }
        m = mnew;
    }

    // Block combine: 8 warp-partials -> one chunk-partial.
    if (lane == 0) { sm[w] = m; sden[w] = den; }
    float4* sv = (float4*)svec[w];
#pragma unroll
    for (int i = 0; i < 4; i++) sv[lane + 32 * i] = acc[i];
    __syncthreads();

    float M = sm[0];
#pragma unroll
    for (int i = 1; i < 8; i++) M = fmaxf(M, sm[i]);
    float wsc[8];
    float denb = 0.f;
#pragma unroll
    for (int i = 0; i < 8; i++) { wsc[i] = expf(sm[i] - M); denb = fmaf(wsc[i], sden[i], denb); }

    int tid = threadIdx.x;
    float* outp = g_ppart + (size_t)(b * NCHUNK + ch) * Dq;
#pragma unroll
    for (int rep = 0; rep < 2; rep++) {
        int d = tid + rep * 256;
        float v = 0.f;
#pragma unroll
        for (int i = 0; i < 8; i++) v = fmaf(wsc[i], svec[i][d], v);
        outp[d] = v;
    }
    if (tid == 0) g_meta[b * NCHUNK + ch] = make_float2(M, denb);
}

// ---------------------------------------------------------------------------
// K3: combine NCHUNK partials per b -> pooled[b,:]. grid = B, block = 128.
// ---------------------------------------------------------------------------
__global__ void k_combine() {
    int b = blockIdx.x, tid = threadIdx.x;
    float2 mt[NCHUNK];
#pragma unroll
    for (int i = 0; i < NCHUNK; i++) mt[i] = g_meta[b * NCHUNK + i];
    float M = mt[0].x;
#pragma unroll
    for (int i = 1; i < NCHUNK; i++) M = fmaxf(M, mt[i].x);
    float den = 0.f;
    float sc[NCHUNK];
#pragma unroll
    for (int i = 0; i < NCHUNK; i++) { sc[i] = expf(mt[i].x - M); den = fmaf(sc[i], mt[i].y, den); }
    float inv_den = 1.f / den;

    const float4* part = (const float4*)(g_ppart + (size_t)b * NCHUNK * Dq);
    float4 acc = make_float4(0.f, 0.f, 0.f, 0.f);
#pragma unroll
    for (int i = 0; i < NCHUNK; i++) {
        float4 p = part[(size_t)i * (Dq / 4) + tid];
        acc.x = fmaf(sc[i], p.x, acc.x);
        acc.y = fmaf(sc[i], p.y, acc.y);
        acc.z = fmaf(sc[i], p.z, acc.z);
        acc.w = fmaf(sc[i], p.w, acc.w);
    }
    acc.x *= inv_den; acc.y *= inv_den; acc.z *= inv_den; acc.w *= inv_den;
    ((float4*)(g_pooled + (size_t)b * Dq))[tid] = acc;
}

// ---------------------------------------------------------------------------
// K4: logits = pooled [B,D] @ txtn^T [D,C]. 32x64 tile, BK=32, 256 thr,
// 2x4 per thread. grid = (C/64, B/32) = 128 blocks.
// ---------------------------------------------------------------------------
__global__ void k_gemm() {
    __shared__ float As[32][36];
    __shared__ float Bs[32][68];
    int tid = threadIdx.x;
    int c0 = blockIdx.x * 64;
    int b0 = blockIdx.y * 32;
    int tx = tid & 15, ty = tid >> 4;

    float acc[2][4];
#pragma unroll
    for (int i = 0; i < 2; i++)
#pragma unroll
        for (int j = 0; j < 4; j++) acc[i][j] = 0.f;

    for (int k0 = 0; k0 < Dq; k0 += 32) {
#pragma unroll
        for (int i = 0; i < 4; i++) {
            int idx = tid + i * 256;
            int r = idx >> 5, kk = idx & 31;
            As[kk][r] = g_pooled[(size_t)(b0 + r) * Dq + k0 + kk];
        }
#pragma unroll
        for (int i = 0; i < 8; i++) {
            int idx = tid + i * 256;
            int r = idx >> 5, kk = idx & 31;
            Bs[kk][r] = g_txtn[(size_t)(c0 + r) * Dq + k0 + kk];
        }
        __syncthreads();
#pragma unroll
        for (int kk = 0; kk < 32; kk++) {
            float a0 = As[kk][ty * 2];
            float a1 = As[kk][ty * 2 + 1];
            float4 b4 = *(const float4*)&Bs[kk][tx * 4];
            acc[0][0] = fmaf(a0, b4.x, acc[0][0]);
            acc[0][1] = fmaf(a0, b4.y, acc[0][1]);
            acc[0][2] = fmaf(a0, b4.z, acc[0][2]);
            acc[0][3] = fmaf(a0, b4.w, acc[0][3]);
            acc[1][0] = fmaf(a1, b4.x, acc[1][0]);
            acc[1][1] = fmaf(a1, b4.y, acc[1][1]);
            acc[1][2] = fmaf(a1, b4.z, acc[1][2]);
            acc[1][3] = fmaf(a1, b4.w, acc[1][3]);
        }
        __syncthreads();
    }
#pragma unroll
    for (int i = 0; i < 2; i++)
#pragma unroll
        for (int j = 0; j < 4; j++)
            g_logits[(size_t)(b0 + ty * 2 + i) * Cq + c0 + tx * 4 + j] = acc[i][j];
}

// ---------------------------------------------------------------------------
// K5: cross entropy + mean via atomicAdd into out (zeroed by K1).
// grid = B, block = 256.
// ---------------------------------------------------------------------------
__global__ void k_ce(const float* __restrict__ p_log_tau,
                     const int* __restrict__ gt,
                     float* __restrict__ out) {
    __shared__ float red[256];
    int b = blockIdx.x, tid = threadIdx.x;
    float tau = expf(*p_log_tau);
    tau = fminf(fmaxf(tau, 0.01f), 1.0f);
    float inv = 1.f / tau;

    float l[4];
    float mx = -1e30f;
#pragma unroll
    for (int i = 0; i < 4; i++) {
        l[i] = g_logits[(size_t)b * Cq + tid + i * 256] * inv;
        mx = fmaxf(mx, l[i]);
    }
    red[tid] = mx;
    __syncthreads();
#pragma unroll
    for (int s = 128; s; s >>= 1) {
        if (tid < s) red[tid] = fmaxf(red[tid], red[tid + s]);
        __syncthreads();
    }
    mx = red[0];
    __syncthreads();

    float sum = 0.f;
#pragma unroll
    for (int i = 0; i < 4; i++) sum += expf(l[i] - mx);
    red[tid] = sum;
    __syncthreads();
#pragma unroll
    for (int s = 128; s; s >>= 1) {
        if (tid < s) red[tid] += red[tid + s];
        __syncthreads();
    }
    if (tid == 0) {
        int g = gt[b];
        float xg = g_logits[(size_t)b * Cq + g] * inv;
        float nll = logf(red[0]) + mx - xg;
        atomicAdd(out, nll * (1.0f / (float)Bq));
    }
}

// ---------------------------------------------------------------------------
extern "C" void kernel_launch(void* const* d_in, const int* in_sizes, int n_in,
                              void* d_out, int out_size) {
    const float* toks         = (const float*)d_in[0];  // [B,N,D] f32
    const float* txt          = (const float*)d_in[1];  // [C,D]   f32
    const float* log_tau      = (const float*)d_in[2];  // scalar
    const float* log_attn_tau = (const float*)d_in[3];  // scalar
    const int*   gt           = (const int*)d_in[4];    // [B] int32
    float* out = (float*)d_out;

    k_txtnorm<<<Cq / 8, 256>>>(txt, out);
    dim3 gf(NCHUNK, Bq);
    k_fused<<<gf, 256>>>(toks, gt, log_attn_tau);
    k_combine<<<Bq, 128>>>();
    dim3 gg(Cq / 64, Bq / 32);
    k_gemm<<<gg, 256>>>();
    k_ce<<<Bq, 256>>>(log_tau, gt, out);
}

// round 4
// speedup vs baseline: 2.1339x; 1.1422x over previous
#include <cuda_runtime.h>
#include <math.h>

#define Bq 256
#define Nq 256
#define Dq 512
#define Cq 1024
#define NCHUNK 8
#define CH_ROWS (Nq / NCHUNK)   // 32 rows per fused block
#define KSPLIT 4
#define KCH (Dq / KSPLIT)       // 128

// Scratch (device globals — no allocation allowed)
__device__ float  g_txtn[Cq * Dq];                 // normalized text (2 MB)
__device__ float  g_ppart[Bq * NCHUNK * Dq];       // partial weighted sums (4 MB)
__device__ float2 g_meta[Bq * NCHUNK];             // (m, den) per partial
__device__ float  g_pooled[Bq * Dq];               // pooled normalized tokens
__device__ float  g_lpart[KSPLIT * Bq * Cq];       // partial logits (4 MB)

__device__ __forceinline__ void warp_sum2(float& a, float& b) {
#pragma unroll
    for (int o = 16; o; o >>= 1) {
        a += __shfl_xor_sync(0xffffffffu, a, o);
        b += __shfl_xor_sync(0xffffffffu, b, o);
    }
}

// ---------------------------------------------------------------------------
// K1: L2-normalize text features; also zero the output scalar (for K5 atomics).
// One warp per row. grid = C/8, block = 256.
// ---------------------------------------------------------------------------
__global__ void k_txtnorm(const float* __restrict__ txt, float* __restrict__ out) {
    if (blockIdx.x == 0 && threadIdx.x == 0) out[0] = 0.f;
    int w = threadIdx.x >> 5, lane = threadIdx.x & 31;
    int row = blockIdx.x * 8 + w;
    const float4* src = (const float4*)(txt + (size_t)row * Dq);
    float4* dst = (float4*)(g_txtn + (size_t)row * Dq);
    float4 v[4];
    float ss = 0.f, dummy = 0.f;
#pragma unroll
    for (int i = 0; i < 4; i++) {
        v[i] = src[lane + 32 * i];
        ss += v[i].x * v[i].x + v[i].y * v[i].y + v[i].z * v[i].z + v[i].w * v[i].w;
    }
    warp_sum2(ss, dummy);
    float rn = 1.f / fmaxf(sqrtf(ss), 1e-12f);
#pragma unroll
    for (int i = 0; i < 4; i++) {
        float4 o;
        o.x = v[i].x * rn; o.y = v[i].y * rn; o.z = v[i].z * rn; o.w = v[i].w * rn;
        dst[lane + 32 * i] = o;
    }
}

// ---------------------------------------------------------------------------
// K2 (fused streaming pass): online softmax-weighted pooling, single read of
// toks (128 MB). grid = (NCHUNK, B) = 2048 blocks, block = 256 (8 warps x 4).
// ---------------------------------------------------------------------------
__global__ void k_fused(const float* __restrict__ toks,
                        const int* __restrict__ gt,
                        const float* __restrict__ p_log_attn_tau) {
    __shared__ float sm[8], sden[8];
    __shared__ float svec[8][Dq];

    int ch = blockIdx.x, b = blockIdx.y;
    int w = threadIdx.x >> 5, lane = threadIdx.x & 31;

    float at = expf(*p_log_attn_tau);
    at = fminf(fmaxf(at, 0.01f), 1.0f);
    float inv_at = 1.f / at;

    int g = __ldg(&gt[b]);
    const float4* xrow = (const float4*)(g_txtn + (size_t)g * Dq);
    float4 xv[4];
#pragma unroll
    for (int i = 0; i < 4; i++) xv[i] = xrow[lane + 32 * i];

    int row0 = b * Nq + ch * CH_ROWS + w * 4;     // this warp's 4 rows
    const float4* base = (const float4*)(toks + (size_t)row0 * Dq);

    float m = -1e30f, den = 0.f;
    float4 acc[4];
#pragma unroll
    for (int i = 0; i < 4; i++) acc[i] = make_float4(0.f, 0.f, 0.f, 0.f);

#pragma unroll
    for (int r = 0; r < 4; r++) {
        float4 tv[4];
#pragma unroll
        for (int i = 0; i < 4; i++)
            tv[i] = __ldcs(&base[(size_t)r * (Dq / 4) + lane + 32 * i]);
        float ss = 0.f, dp = 0.f;
#pragma unroll
        for (int i = 0; i < 4; i++) {
            ss += tv[i].x * tv[i].x + tv[i].y * tv[i].y + tv[i].z * tv[i].z + tv[i].w * tv[i].w;
            dp += tv[i].x * xv[i].x + tv[i].y * xv[i].y + tv[i].z * xv[i].z + tv[i].w * xv[i].w;
        }
        warp_sum2(ss, dp);
        float rn = 1.f / fmaxf(sqrtf(ss), 1e-12f);
        float s = dp * rn * inv_at;
        float mnew = fmaxf(m, s);
        float scale = expf(m - mnew);   // 0 on first row
        float e = expf(s - mnew);
        den = den * scale + e;
        float ern = e * rn;
#pragma unroll
        for (int i = 0; i < 4; i++) {
            acc[i].x = fmaf(ern, tv[i].x, acc[i].x * scale);
            acc[i].y = fmaf(ern, tv[i].y, acc[i].y * scale);
            acc[i].z = fmaf(ern, tv[i].z, acc[i].z * scale);
            acc[i].w = fmaf(ern, tv[i].w, acc[i].w * scale);
        }
        m = mnew;
    }

    // Block combine: 8 warp-partials -> one chunk-partial.
    if (lane == 0) { sm[w] = m; sden[w] = den; }
    float4* sv = (float4*)svec[w];
#pragma unroll
    for (int i = 0; i < 4; i++) sv[lane + 32 * i] = acc[i];
    __syncthreads();

    float M = sm[0];
#pragma unroll
    for (int i = 1; i < 8; i++) M = fmaxf(M, sm[i]);
    float wsc[8];
    float denb = 0.f;
#pragma unroll
    for (int i = 0; i < 8; i++) { wsc[i] = expf(sm[i] - M); denb = fmaf(wsc[i], sden[i], denb); }

    int tid = threadIdx.x;
    float* outp = g_ppart + (size_t)(b * NCHUNK + ch) * Dq;
#pragma unroll
    for (int rep = 0; rep < 2; rep++) {
        int d = tid + rep * 256;
        float v = 0.f;
#pragma unroll
        for (int i = 0; i < 8; i++) v = fmaf(wsc[i], svec[i][d], v);
        outp[d] = v;
    }
    if (tid == 0) g_meta[b * NCHUNK + ch] = make_float2(M, denb);
}

// ---------------------------------------------------------------------------
// K3: combine NCHUNK partials per b -> pooled[b,:]. grid = B, block = 128.
// ---------------------------------------------------------------------------
__global__ void k_combine() {
    int b = blockIdx.x, tid = threadIdx.x;
    float2 mt[NCHUNK];
#pragma unroll
    for (int i = 0; i < NCHUNK; i++) mt[i] = g_meta[b * NCHUNK + i];
    float M = mt[0].x;
#pragma unroll
    for (int i = 1; i < NCHUNK; i++) M = fmaxf(M, mt[i].x);
    float den = 0.f;
    float sc[NCHUNK];
#pragma unroll
    for (int i = 0; i < NCHUNK; i++) { sc[i] = expf(mt[i].x - M); den = fmaf(sc[i], mt[i].y, den); }
    float inv_den = 1.f / den;

    const float4* part = (const float4*)(g_ppart + (size_t)b * NCHUNK * Dq);
    float4 acc = make_float4(0.f, 0.f, 0.f, 0.f);
#pragma unroll
    for (int i = 0; i < NCHUNK; i++) {
        float4 p = part[(size_t)i * (Dq / 4) + tid];
        acc.x = fmaf(sc[i], p.x, acc.x);
        acc.y = fmaf(sc[i], p.y, acc.y);
        acc.z = fmaf(sc[i], p.z, acc.z);
        acc.w = fmaf(sc[i], p.w, acc.w);
    }
    acc.x *= inv_den; acc.y *= inv_den; acc.z *= inv_den; acc.w *= inv_den;
    ((float4*)(g_pooled + (size_t)b * Dq))[tid] = acc;
}

// ---------------------------------------------------------------------------
// K4: partial logits = pooled[:, kchunk] @ txtn[:, kchunk]^T.
// 32b x 64c tile, BK=32, 256 thr, 2x4 micro. grid = (C/64, B/32, KSPLIT)
// = 512 blocks. Writes g_lpart[ks].
// ---------------------------------------------------------------------------
__global__ void k_gemm() {
    __shared__ float As[32][36];
    __shared__ float Bs[32][68];
    int tid = threadIdx.x;
    int c0 = blockIdx.x * 64;
    int b0 = blockIdx.y * 32;
    int ks = blockIdx.z;
    int kbase = ks * KCH;
    int tx = tid & 15, ty = tid >> 4;

    float acc[2][4];
#pragma unroll
    for (int i = 0; i < 2; i++)
#pragma unroll
        for (int j = 0; j < 4; j++) acc[i][j] = 0.f;

    for (int k0 = kbase; k0 < kbase + KCH; k0 += 32) {
#pragma unroll
        for (int i = 0; i < 4; i++) {
            int idx = tid + i * 256;
            int r = idx >> 5, kk = idx & 31;
            As[kk][r] = g_pooled[(size_t)(b0 + r) * Dq + k0 + kk];
        }
#pragma unroll
        for (int i = 0; i < 8; i++) {
            int idx = tid + i * 256;
            int r = idx >> 5, kk = idx & 31;
            Bs[kk][r] = g_txtn[(size_t)(c0 + r) * Dq + k0 + kk];
        }
        __syncthreads();
#pragma unroll
        for (int kk = 0; kk < 32; kk++) {
            float2 a2 = *(const float2*)&As[kk][ty * 2];
            float4 b4 = *(const float4*)&Bs[kk][tx * 4];
            acc[0][0] = fmaf(a2.x, b4.x, acc[0][0]);
            acc[0][1] = fmaf(a2.x, b4.y, acc[0][1]);
            acc[0][2] = fmaf(a2.x, b4.z, acc[0][2]);
            acc[0][3] = fmaf(a2.x, b4.w, acc[0][3]);
            acc[1][0] = fmaf(a2.y, b4.x, acc[1][0]);
            acc[1][1] = fmaf(a2.y, b4.y, acc[1][1]);
            acc[1][2] = fmaf(a2.y, b4.z, acc[1][2]);
            acc[1][3] = fmaf(a2.y, b4.w, acc[1][3]);
        }
        __syncthreads();
    }
    float* dst = g_lpart + ((size_t)ks * Bq) * Cq;
#pragma unroll
    for (int i = 0; i < 2; i++)
#pragma unroll
        for (int j = 0; j < 4; j++)
            dst[(size_t)(b0 + ty * 2 + i) * Cq + c0 + tx * 4 + j] = acc[i][j];
}

// ---------------------------------------------------------------------------
// K5: cross entropy (summing KSPLIT logit partials) + mean via atomicAdd.
// grid = B, block = 256.
// ---------------------------------------------------------------------------
__global__ void k_ce(const float* __restrict__ p_log_tau,
                     const int* __restrict__ gt,
                     float* __restrict__ out) {
    __shared__ float red[256];
    int b = blockIdx.x, tid = threadIdx.x;
    float tau = expf(*p_log_tau);
    tau = fminf(fmaxf(tau, 0.01f), 1.0f);
    float inv = 1.f / tau;

    float l[4];
    float mx = -1e30f;
#pragma unroll
    for (int i = 0; i < 4; i++) {
        int idx = tid + i * 256;
        float v = 0.f;
#pragma unroll
        for (int ks = 0; ks < KSPLIT; ks++)
            v += g_lpart[((size_t)ks * Bq + b) * Cq + idx];
        l[i] = v * inv;
        mx = fmaxf(mx, l[i]);
    }
    red[tid] = mx;
    __syncthreads();
#pragma unroll
    for (int s = 128; s; s >>= 1) {
        if (tid < s) red[tid] = fmaxf(red[tid], red[tid + s]);
        __syncthreads();
    }
    mx = red[0];
    __syncthreads();

    float sum = 0.f;
#pragma unroll
    for (int i = 0; i < 4; i++) sum += expf(l[i] - mx);
    red[tid] = sum;
    __syncthreads();
#pragma unroll
    for (int s = 128; s; s >>= 1) {
        if (tid < s) red[tid] += red[tid + s];
        __syncthreads();
    }
    if (tid == 0) {
        int g = gt[b];
        float xg = 0.f;
#pragma unroll
        for (int ks = 0; ks < KSPLIT; ks++)
            xg += g_lpart[((size_t)ks * Bq + b) * Cq + g];
        xg *= inv;
        float nll = logf(red[0]) + mx - xg;
        atomicAdd(out, nll * (1.0f / (float)Bq));
    }
}

// ---------------------------------------------------------------------------
extern "C" void kernel_launch(void* const* d_in, const int* in_sizes, int n_in,
                              void* d_out, int out_size) {
    const float* toks         = (const float*)d_in[0];  // [B,N,D] f32
    const float* txt          = (const float*)d_in[1];  // [C,D]   f32
    const float* log_tau      = (const float*)d_in[2];  // scalar
    const float* log_attn_tau = (const float*)d_in[3];  // scalar
    const int*   gt           = (const int*)d_in[4];    // [B] int32
    float* out = (float*)d_out;

    k_txtnorm<<<Cq / 8, 256>>>(txt, out);
    dim3 gf(NCHUNK, Bq);
    k_fused<<<gf, 256>>>(toks, gt, log_attn_tau);
    k_combine<<<Bq, 128>>>();
    dim3 gg(Cq / 64, Bq / 32, KSPLIT);
    k_gemm<<<gg, 256>>>();
    k_ce<<<Bq, 256>>>(log_tau, gt, out);
}

// round 5
// speedup vs baseline: 2.3861x; 1.1182x over previous
#include <cuda_runtime.h>
#include <math.h>

#define Bq 256
#define Nq 256
#define Dq 512
#define Cq 1024
#define NCHUNK 8
#define CH_ROWS (Nq / NCHUNK)   // 32 rows per fused block
#define KSPLIT 8
#define KCH (Dq / KSPLIT)       // 64

// Scratch (device globals — no allocation allowed)
__device__ float  g_txtn[Cq * Dq];                 // normalized text (2 MB)
__device__ float  g_ppart[Bq * NCHUNK * Dq];       // partial weighted sums (4 MB)
__device__ float2 g_meta[Bq * NCHUNK];             // (m, den) per partial
__device__ float  g_pooled[Bq * Dq];               // pooled normalized tokens
__device__ float  g_lpart[KSPLIT * Bq * Cq];       // partial logits (8 MB)

__device__ __forceinline__ void warp_sum2(float& a, float& b) {
#pragma unroll
    for (int o = 16; o; o >>= 1) {
        a += __shfl_xor_sync(0xffffffffu, a, o);
        b += __shfl_xor_sync(0xffffffffu, b, o);
    }
}

__device__ __forceinline__ void warp_sum4(float& a, float& b, float& c, float& d) {
#pragma unroll
    for (int o = 16; o; o >>= 1) {
        a += __shfl_xor_sync(0xffffffffu, a, o);
        b += __shfl_xor_sync(0xffffffffu, b, o);
        c += __shfl_xor_sync(0xffffffffu, c, o);
        d += __shfl_xor_sync(0xffffffffu, d, o);
    }
}

// ---------------------------------------------------------------------------
// K1: L2-normalize text features; also zero the output scalar (for K5 atomic).
// One warp per row. grid = C/8, block = 256.
// ---------------------------------------------------------------------------
__global__ void k_txtnorm(const float* __restrict__ txt, float* __restrict__ out) {
    if (blockIdx.x == 0 && threadIdx.x == 0) out[0] = 0.f;
    int w = threadIdx.x >> 5, lane = threadIdx.x & 31;
    int row = blockIdx.x * 8 + w;
    const float4* src = (const float4*)(txt + (size_t)row * Dq);
    float4* dst = (float4*)(g_txtn + (size_t)row * Dq);
    float4 v[4];
    float ss = 0.f, dummy = 0.f;
#pragma unroll
    for (int i = 0; i < 4; i++) {
        v[i] = src[lane + 32 * i];
        ss += v[i].x * v[i].x + v[i].y * v[i].y + v[i].z * v[i].z + v[i].w * v[i].w;
    }
    warp_sum2(ss, dummy);
    float rn = 1.f / fmaxf(sqrtf(ss), 1e-12f);
#pragma unroll
    for (int i = 0; i < 4; i++) {
        float4 o;
        o.x = v[i].x * rn; o.y = v[i].y * rn; o.z = v[i].z * rn; o.w = v[i].w * rn;
        dst[lane + 32 * i] = o;
    }
}

// ---------------------------------------------------------------------------
// K2 (fused streaming pass): online softmax-weighted pooling, single read of
// toks (128 MB). Two rows processed per iteration for 2x MLP.
// grid = (NCHUNK, B) = 2048 blocks, block = 256 (8 warps x 4 rows).
// ---------------------------------------------------------------------------
__global__ void k_fused(const float* __restrict__ toks,
                        const int* __restrict__ gt,
                        const float* __restrict__ p_log_attn_tau) {
    __shared__ float sm[8], sden[8];
    __shared__ float svec[8][Dq];

    int ch = blockIdx.x, b = blockIdx.y;
    int w = threadIdx.x >> 5, lane = threadIdx.x & 31;

    float at = expf(*p_log_attn_tau);
    at = fminf(fmaxf(at, 0.01f), 1.0f);
    float inv_at = 1.f / at;

    int g = __ldg(&gt[b]);
    const float4* xrow = (const float4*)(g_txtn + (size_t)g * Dq);
    float4 xv[4];
#pragma unroll
    for (int i = 0; i < 4; i++) xv[i] = xrow[lane + 32 * i];

    int row0 = b * Nq + ch * CH_ROWS + w * 4;     // this warp's 4 rows
    const float4* base = (const float4*)(toks + (size_t)row0 * Dq);

    float m = -1e30f, den = 0.f;
    float4 acc[4];
#pragma unroll
    for (int i = 0; i < 4; i++) acc[i] = make_float4(0.f, 0.f, 0.f, 0.f);

#pragma unroll
    for (int rp = 0; rp < 2; rp++) {
        float4 t0[4], t1[4];
#pragma unroll
        for (int i = 0; i < 4; i++)
            t0[i] = __ldcs(&base[(size_t)(2 * rp) * (Dq / 4) + lane + 32 * i]);
#pragma unroll
        for (int i = 0; i < 4; i++)
            t1[i] = __ldcs(&base[(size_t)(2 * rp + 1) * (Dq / 4) + lane + 32 * i]);

        float ss0 = 0.f, dp0 = 0.f, ss1 = 0.f, dp1 = 0.f;
#pragma unroll
        for (int i = 0; i < 4; i++) {
            ss0 += t0[i].x * t0[i].x + t0[i].y * t0[i].y + t0[i].z * t0[i].z + t0[i].w * t0[i].w;
            dp0 += t0[i].x * xv[i].x + t0[i].y * xv[i].y + t0[i].z * xv[i].z + t0[i].w * xv[i].w;
            ss1 += t1[i].x * t1[i].x + t1[i].y * t1[i].y + t1[i].z * t1[i].z + t1[i].w * t1[i].w;
            dp1 += t1[i].x * xv[i].x + t1[i].y * xv[i].y + t1[i].z * xv[i].z + t1[i].w * xv[i].w;
        }
        warp_sum4(ss0, dp0, ss1, dp1);

        float rn0 = 1.f / fmaxf(sqrtf(ss0), 1e-12f);
        float rn1 = 1.f / fmaxf(sqrtf(ss1), 1e-12f);
        float s0 = dp0 * rn0 * inv_at;
        float s1 = dp1 * rn1 * inv_at;
        float mnew = fmaxf(m, fmaxf(s0, s1));
        float scale = expf(m - mnew);      // 0 on first pair
        float e0 = expf(s0 - mnew);
        float e1 = expf(s1 - mnew);
        den = den * scale + e0 + e1;
        float c0 = e0 * rn0, c1 = e1 * rn1;
#pragma unroll
        for (int i = 0; i < 4; i++) {
            acc[i].x = fmaf(c1, t1[i].x, fmaf(c0, t0[i].x, acc[i].x * scale));
            acc[i].y = fmaf(c1, t1[i].y, fmaf(c0, t0[i].y, acc[i].y * scale));
            acc[i].z = fmaf(c1, t1[i].z, fmaf(c0, t0[i].z, acc[i].z * scale));
            acc[i].w = fmaf(c1, t1[i].w, fmaf(c0, t0[i].w, acc[i].w * scale));
        }
        m = mnew;
    }

    // Block combine: 8 warp-partials -> one chunk-partial.
    if (lane == 0) { sm[w] = m; sden[w] = den; }
    float4* sv = (float4*)svec[w];
#pragma unroll
    for (int i = 0; i < 4; i++) sv[lane + 32 * i] = acc[i];
    __syncthreads();

    float M = sm[0];
#pragma unroll
    for (int i = 1; i < 8; i++) M = fmaxf(M, sm[i]);
    float wsc[8];
    float denb = 0.f;
#pragma unroll
    for (int i = 0; i < 8; i++) { wsc[i] = expf(sm[i] - M); denb = fmaf(wsc[i], sden[i], denb); }

    int tid = threadIdx.x;
    float* outp = g_ppart + (size_t)(b * NCHUNK + ch) * Dq;
#pragma unroll
    for (int rep = 0; rep < 2; rep++) {
        int d = tid + rep * 256;
        float v = 0.f;
#pragma unroll
        for (int i = 0; i < 8; i++) v = fmaf(wsc[i], svec[i][d], v);
        outp[d] = v;
    }
    if (tid == 0) g_meta[b * NCHUNK + ch] = make_float2(M, denb);
}

// ---------------------------------------------------------------------------
// K3: combine NCHUNK partials per b -> pooled[b,:]. grid = B, block = 128.
// ---------------------------------------------------------------------------
__global__ void k_combine() {
    int b = blockIdx.x, tid = threadIdx.x;
    float2 mt[NCHUNK];
#pragma unroll
    for (int i = 0; i < NCHUNK; i++) mt[i] = g_meta[b * NCHUNK + i];
    float M = mt[0].x;
#pragma unroll
    for (int i = 1; i < NCHUNK; i++) M = fmaxf(M, mt[i].x);
    float den = 0.f;
    float sc[NCHUNK];
#pragma unroll
    for (int i = 0; i < NCHUNK; i++) { sc[i] = expf(mt[i].x - M); den = fmaf(sc[i], mt[i].y, den); }
    float inv_den = 1.f / den;

    const float4* part = (const float4*)(g_ppart + (size_t)b * NCHUNK * Dq);
    float4 acc = make_float4(0.f, 0.f, 0.f, 0.f);
#pragma unroll
    for (int i = 0; i < NCHUNK; i++) {
        float4 p = part[(size_t)i * (Dq / 4) + tid];
        acc.x = fmaf(sc[i], p.x, acc.x);
        acc.y = fmaf(sc[i], p.y, acc.y);
        acc.z = fmaf(sc[i], p.z, acc.z);
        acc.w = fmaf(sc[i], p.w, acc.w);
    }
    acc.x *= inv_den; acc.y *= inv_den; acc.z *= inv_den; acc.w *= inv_den;
    ((float4*)(g_pooled + (size_t)b * Dq))[tid] = acc;
}

// ---------------------------------------------------------------------------
// K4: partial logits = pooled[:, kchunk] @ txtn[:, kchunk]^T.
// 64b x 64c tile, BK=32, 256 thr, 4x4 micro. grid = (C/64, B/64, KSPLIT)
// = (16, 4, 8) = 512 blocks. Writes g_lpart[ks].
// ---------------------------------------------------------------------------
__global__ void k_gemm() {
    __shared__ float As[32][68];
    __shared__ float Bs[32][68];
    int tid = threadIdx.x;
    int c0 = blockIdx.x * 64;
    int b0 = blockIdx.y * 64;
    int ks = blockIdx.z;
    int kbase = ks * KCH;
    int tx = tid & 15, ty = tid >> 4;   // 16x16 thread grid, 4x4 each

    float acc[4][4];
#pragma unroll
    for (int i = 0; i < 4; i++)
#pragma unroll
        for (int j = 0; j < 4; j++) acc[i][j] = 0.f;

    for (int k0 = kbase; k0 < kbase + KCH; k0 += 32) {
#pragma unroll
        for (int i = 0; i < 8; i++) {
            int idx = tid + i * 256;            // 2048 elems: 64 rows x 32 k
            int r = idx >> 5, kk = idx & 31;
            As[kk][r] = g_pooled[(size_t)(b0 + r) * Dq + k0 + kk];
            Bs[kk][r] = g_txtn[(size_t)(c0 + r) * Dq + k0 + kk];
        }
        __syncthreads();
#pragma unroll
        for (int kk = 0; kk < 32; kk++) {
            float4 a4 = *(const float4*)&As[kk][ty * 4];
            float4 b4 = *(const float4*)&Bs[kk][tx * 4];
            float a[4] = {a4.x, a4.y, a4.z, a4.w};
            float bb[4] = {b4.x, b4.y, b4.z, b4.w};
#pragma unroll
            for (int i = 0; i < 4; i++)
#pragma unroll
                for (int j = 0; j < 4; j++)
                    acc[i][j] = fmaf(a[i], bb[j], acc[i][j]);
        }
        __syncthreads();
    }
    float* dst = g_lpart + ((size_t)ks * Bq) * Cq;
#pragma unroll
    for (int i = 0; i < 4; i++) {
        float4 o = make_float4(acc[i][0], acc[i][1], acc[i][2], acc[i][3]);
        *(float4*)&dst[(size_t)(b0 + ty * 4 + i) * Cq + c0 + tx * 4] = o;
    }
}

// ---------------------------------------------------------------------------
// K5: cross entropy (summing KSPLIT logit partials) + mean via atomicAdd.
// grid = B, block = 256.
// ---------------------------------------------------------------------------
__global__ void k_ce(const float* __restrict__ p_log_tau,
                     const int* __restrict__ gt,
                     float* __restrict__ out) {
    __shared__ float red[256];
    int b = blockIdx.x, tid = threadIdx.x;
    float tau = expf(*p_log_tau);
    tau = fminf(fmaxf(tau, 0.01f), 1.0f);
    float inv = 1.f / tau;

    float l[4];
    float mx = -1e30f;
#pragma unroll
    for (int i = 0; i < 4; i++) {
        int idx = tid + i * 256;
        float v = 0.f;
#pragma unroll
        for (int ks = 0; ks < KSPLIT; ks++)
            v += g_lpart[((size_t)ks * Bq + b) * Cq + idx];
        l[i] = v * inv;
        mx = fmaxf(mx, l[i]);
    }
    red[tid] = mx;
    __syncthreads();
#pragma unroll
    for (int s = 128; s; s >>= 1) {
        if (tid < s) red[tid] = fmaxf(red[tid], red[tid + s]);
        __syncthreads();
    }
    mx = red[0];
    __syncthreads();

    float sum = 0.f;
#pragma unroll
    for (int i = 0; i < 4; i++) sum += expf(l[i] - mx);
    red[tid] = sum;
    __syncthreads();
#pragma unroll
    for (int s = 128; s; s >>= 1) {
        if (tid < s) red[tid] += red[tid + s];
        __syncthreads();
    }
    if (tid == 0) {
        int g = gt[b];
        float xg = 0.f;
#pragma unroll
        for (int ks = 0; ks < KSPLIT; ks++)
            xg += g_lpart[((size_t)ks * Bq + b) * Cq + g];
        xg *= inv;
        float nll = logf(red[0]) + mx - xg;
        atomicAdd(out, nll * (1.0f / (float)Bq));
    }
}

// ---------------------------------------------------------------------------
extern "C" void kernel_launch(void* const* d_in, const int* in_sizes, int n_in,
                              void* d_out, int out_size) {
    const float* toks         = (const float*)d_in[0];  // [B,N,D] f32
    const float* txt          = (const float*)d_in[1];  // [C,D]   f32
    const float* log_tau      = (const float*)d_in[2];  // scalar
    const float* log_attn_tau = (const float*)d_in[3];  // scalar
    const int*   gt           = (const int*)d_in[4];    // [B] int32
    float* out = (float*)d_out;

    k_txtnorm<<<Cq / 8, 256>>>(txt, out);
    dim3 gf(NCHUNK, Bq);
    k_fused<<<gf, 256>>>(toks, gt, log_attn_tau);
    k_combine<<<Bq, 128>>>();
    dim3 gg(Cq / 64, Bq / 64, KSPLIT);
    k_gemm<<<gg, 256>>>();
    k_ce<<<Bq, 256>>>(log_tau, gt, out);
}